// round 14
// baseline (speedup 1.0000x reference)
#include <cuda_runtime.h>
#include <cuda_fp16.h>
#include <cstdint>

#define BV 8
#define NV 2048
#define EV 256
#define HV 512
#define MROWS (BV*NV)   // 16384

// ---------------- scratch (static device globals) ----------------
__device__ __half g_A16[(size_t)MROWS * EV];     // fp16 gathered embeddings
__device__ __half g_W1h[HV * EV];
__device__ __half g_W2h[HV * HV];
__device__ __half g_h16[(size_t)MROWS * HV];     // relu(emb@W1+b1), fp16
__device__ float  g_hidden[(size_t)MROWS * HV];  // fp32 hidden (witness)
__device__ __half g_hid16[(size_t)MROWS * HV];   // fp16 hidden (sim input)
__device__ float  g_ss[MROWS];                   // per-row sum of squares
__device__ float g_c[BV * NV];
__device__ float g_wit[BV * HV];

// ---------------- helpers ----------------
__device__ __forceinline__ uint32_t smem_u32(const void* p) {
    uint32_t a;
    asm("{ .reg .u64 t; cvta.to.shared.u64 t, %1; cvt.u32.u64 %0, t; }" : "=r"(a) : "l"(p));
    return a;
}
__device__ __forceinline__ void mma_f16(float* c, const uint32_t* a, const uint32_t* b) {
    asm volatile("mma.sync.aligned.m16n8k16.row.col.f32.f16.f16.f32 "
                 "{%0,%1,%2,%3}, {%4,%5,%6,%7}, {%8,%9}, {%0,%1,%2,%3};"
                 : "+f"(c[0]), "+f"(c[1]), "+f"(c[2]), "+f"(c[3])
                 : "r"(a[0]), "r"(a[1]), "r"(a[2]), "r"(a[3]),
                   "r"(b[0]), "r"(b[1]));
}
__device__ __forceinline__ void mma_f16h(uint32_t* c, const uint32_t* a, const uint32_t* b) {
    asm volatile("mma.sync.aligned.m16n8k16.row.col.f16.f16.f16.f16 "
                 "{%0,%1}, {%2,%3,%4,%5}, {%6,%7}, {%0,%1};"
                 : "+r"(c[0]), "+r"(c[1])
                 : "r"(a[0]), "r"(a[1]), "r"(a[2]), "r"(a[3]),
                   "r"(b[0]), "r"(b[1]));
}
#define LDSM4(r0, r1, r2, r3, addr) \
    asm volatile("ldmatrix.sync.aligned.m8n8.x4.shared.b16 {%0,%1,%2,%3}, [%4];" \
                 : "=r"(r0), "=r"(r1), "=r"(r2), "=r"(r3) : "r"(addr))

// ---- TMA bulk copy + mbarrier (sm_90 baseline PTX, no 'a' gating) ----
#define BULK128(dst, gsrc, mbar) \
    asm volatile("cp.async.bulk.shared::cluster.global.mbarrier::complete_tx::bytes " \
                 "[%0], [%1], %2, [%3];" \
                 :: "r"(dst), "l"(gsrc), "r"(128u), "r"(mbar) : "memory")
#define MBAR_INIT(a, n) \
    asm volatile("mbarrier.init.shared.b64 [%0], %1;" :: "r"(a), "r"(n) : "memory")
#define MBAR_EXPECT(a, n) \
    asm volatile("mbarrier.arrive.expect_tx.shared.b64 _, [%0], %1;" :: "r"(a), "r"(n) : "memory")
#define MBAR_WAIT(a, p) do { \
    asm volatile("{\n\t.reg .pred P;\n" \
                 "WL_%=:\n\t" \
                 "mbarrier.try_wait.parity.acquire.cta.shared::cta.b64 P, [%0], %1;\n\t" \
                 "@!P bra WL_%=;\n\t}\n" \
                 :: "r"(a), "r"(p) : "memory"); \
} while (0)

// MUFU-free softplus for |x| <= ~1.1 (sim = cosine similarity).
__device__ __forceinline__ float softplus_fast(float x) {
    float u = 0.5f * x;
    float v = u * u;
    float p = fmaf(v, 0.002186948854f, -0.006746031746f);
    p = fmaf(v, p, 0.022222222222f);
    p = fmaf(v, p, -0.083333333333f);
    p = fmaf(v, p, 0.5f);
    return fmaf(v, p, u + 0.69314718056f);
}

// ---------------- fused conversion + zero kernel ----------------
constexpr int EMB_BLK = MROWS / 4;                 // 4096
constexpr int W1_BLK = (HV * EV / 4) / 256;        // 128
constexpr int W2_BLK = (HV * HV / 4) / 256;        // 256
constexpr int Z_TOTAL = BV * NV + BV * HV + MROWS; // 36864
constexpr int Z_BLK = Z_TOTAL / 256;               // 144

__global__ __launch_bounds__(256)
void conv_all_kernel(const int* __restrict__ tokens, const float* __restrict__ emb,
                     const float* __restrict__ W1, const float* __restrict__ W2)
{
    const int blk = blockIdx.x;
    if (blk < EMB_BLK) {
        const int idx = blk * 256 + threadIdx.x;
        const int row = idx >> 6;
        const int t = idx & 63;
        const int tok = tokens[row];
        float4 v = *(const float4*)(emb + (size_t)tok * EV + t * 4);
        size_t o = (size_t)row * EV + t * 4;
        *(__half2*)(g_A16 + o)     = __floats2half2_rn(v.x, v.y);
        *(__half2*)(g_A16 + o + 2) = __floats2half2_rn(v.z, v.w);
    } else if (blk < EMB_BLK + W1_BLK) {
        int i = (blk - EMB_BLK) * 256 + threadIdx.x;
        float4 v = ((const float4*)W1)[i];
        size_t o = (size_t)i * 4;
        *(__half2*)(g_W1h + o)     = __floats2half2_rn(v.x, v.y);
        *(__half2*)(g_W1h + o + 2) = __floats2half2_rn(v.z, v.w);
    } else if (blk < EMB_BLK + W1_BLK + W2_BLK) {
        int i = (blk - EMB_BLK - W1_BLK) * 256 + threadIdx.x;
        float4 v = ((const float4*)W2)[i];
        size_t o = (size_t)i * 4;
        *(__half2*)(g_W2h + o)     = __floats2half2_rn(v.x, v.y);
        *(__half2*)(g_W2h + o + 2) = __floats2half2_rn(v.z, v.w);
    } else {
        int i = (blk - EMB_BLK - W1_BLK - W2_BLK) * 256 + threadIdx.x;
        if (i < BV * NV) g_c[i] = 0.f;
        else if (i < BV * NV + BV * HV) g_wit[i - BV * NV] = 0.f;
        else if (i < Z_TOTAL) g_ss[i - BV * NV - BV * HV] = 0.f;
    }
}

// ============================================================
// Tile geometry: 144B-pitched rows (128B data + 16B pad) -> LDSM
// conflict-free without XOR swizzle; bulk-copy friendly (linear rows).
// ============================================================
constexpr int PITCH = 144;
constexpr int G_A_BYTES = 128 * PITCH;             // 18432
constexpr int G_STAGE = 2 * G_A_BYTES;             // 36864 (A+B, 128 rows each)
constexpr int G_NSTAGE = 3;
constexpr int G_SMEM = G_NSTAGE * G_STAGE;         // 110592 (108 KB)
constexpr uint32_t G_TX = 256 * 128;               // bytes per stage

// ============================================================
// gemm_t: dense GEMMs, fp32 accumulators, TMA-bulk loader.
// MODE 0: relu(A16 @ W1^T + b1) -> g_h16                         (K=256)
// MODE 1: h16 @ W2^T + b2 -> g_hidden fp32 + g_hid16 fp16 + g_ss (K=512)
// ============================================================
template<int MODE>
__global__ __launch_bounds__(256, 2)
void gemm_t(const float* __restrict__ bias)
{
    constexpr int KDIM = (MODE == 0) ? EV : HV;
    constexpr int NC = KDIM / 64;
    extern __shared__ __align__(1024) char smem[];
    const uint32_t sbase = smem_u32(smem);
    __shared__ float sBias[128];
    __shared__ __align__(8) uint64_t s_mbar[G_NSTAGE];
    const uint32_t mb = smem_u32(s_mbar);

    const int tid = threadIdx.x;
    const int lane = tid & 31;
    const int wid = tid >> 5;

    const int rowA = blockIdx.x * 128;
    const int rowB = blockIdx.y * 128;

    const __half* srcA = (MODE == 0) ? g_A16 + (size_t)rowA * KDIM
                                     : g_h16 + (size_t)rowA * KDIM;
    const __half* srcB = (MODE == 0) ? g_W1h + (size_t)rowB * KDIM
                                     : g_W2h + (size_t)rowB * KDIM;
    if (tid < 128) sBias[tid] = bias[blockIdx.y * 128 + tid];
    if (tid == 0) {
#pragma unroll
        for (int s = 0; s < G_NSTAGE; s++) MBAR_INIT(mb + s * 8, 1);
    }
    __syncthreads();

    // ---- bulk stage loader: 1 row (128B) per thread ----
    auto load_stage = [&](int slot, int c) {
        const uint32_t stBase = sbase + slot * G_STAGE;
        const int k0 = c * 64;
        if (tid == 0) MBAR_EXPECT(mb + slot * 8, G_TX);
        const int r = tid;
        const __half* gsrc = (r < 128) ? srcA + (size_t)r * KDIM + k0
                                       : srcB + (size_t)(r - 128) * KDIM + k0;
        uint32_t dst = stBase + ((r < 128) ? r * PITCH
                                           : G_A_BYTES + (r - 128) * PITCH);
        BULK128(dst, gsrc, mb + slot * 8);
    };

    const int warpM = (wid >> 2) * 64;
    const int warpN = (wid & 3) * 32;
    uint32_t aRow[4], bRow[2];
#pragma unroll
    for (int mi = 0; mi < 4; mi++)
        aRow[mi] = (uint32_t)((warpM + mi * 16 + (lane & 15)) * PITCH);
    const int bLocal = (lane & 7) + ((lane >> 4) << 3);
#pragma unroll
    for (int p = 0; p < 2; p++)
        bRow[p] = (uint32_t)((warpN + p * 16 + bLocal) * PITCH);
    const uint32_t aKsel = (uint32_t)((lane >> 4) << 4);
    const uint32_t bKsel = (uint32_t)(((lane >> 3) & 1) << 4);

    float acc[4][4][4];
#pragma unroll
    for (int mi = 0; mi < 4; mi++)
#pragma unroll
        for (int ni = 0; ni < 4; ni++)
#pragma unroll
            for (int k = 0; k < 4; k++) acc[mi][ni][k] = 0.f;

    auto compute_stage = [&](int slot) {
        const uint32_t stBase = sbase + slot * G_STAGE;
        const uint32_t tA = stBase, tB = stBase + G_A_BYTES;
#pragma unroll
        for (int ks = 0; ks < 4; ks++) {
            const uint32_t kk = (uint32_t)(ks * 32);
            uint32_t bh[4][2];
            {
                uint32_t r0, r1, r2, r3;
                LDSM4(r0, r1, r2, r3, tB + bRow[0] + kk + bKsel);
                bh[0][0] = r0; bh[0][1] = r1; bh[1][0] = r2; bh[1][1] = r3;
                LDSM4(r0, r1, r2, r3, tB + bRow[1] + kk + bKsel);
                bh[2][0] = r0; bh[2][1] = r1; bh[3][0] = r2; bh[3][1] = r3;
            }
            uint32_t a[4][4];
#pragma unroll
            for (int mi = 0; mi < 4; mi++)
                LDSM4(a[mi][0], a[mi][1], a[mi][2], a[mi][3],
                      tA + aRow[mi] + kk + aKsel);
#pragma unroll
            for (int mi = 0; mi < 4; mi++)
#pragma unroll
                for (int ni = 0; ni < 4; ni++)
                    mma_f16(acc[mi][ni], a[mi], bh[ni]);
        }
    };

    // ---- mainloop: 3-stage ring, mbarrier-gated ----
    load_stage(0, 0);
    load_stage(1, 1);
    for (int c = 0; c < NC; c++) {
        const int slot = c % G_NSTAGE;
        MBAR_WAIT(mb + slot * 8, (uint32_t)((c / G_NSTAGE) & 1));
        __syncthreads();   // all threads done computing stage c-1 -> slot (c+2)%3 free
        if (c + 2 < NC) load_stage((c + 2) % G_NSTAGE, c + 2);
        compute_stage(slot);
    }

    // ---- epilogue ----
    const int rBase0 = warpM + (lane >> 2);
    const int cBase = warpN + (lane & 3) * 2;

    float ssAcc[4][2];
#pragma unroll
    for (int mi = 0; mi < 4; mi++) { ssAcc[mi][0] = 0.f; ssAcc[mi][1] = 0.f; }
#pragma unroll
    for (int mi = 0; mi < 4; mi++) {
        const int r = rBase0 + mi * 16;
#pragma unroll
        for (int ni = 0; ni < 4; ni++) {
            const int cl = cBase + ni * 8;
            const int gc = blockIdx.y * 128 + cl;
            float v0 = acc[mi][ni][0] + sBias[cl];
            float v1 = acc[mi][ni][1] + sBias[cl + 1];
            float v2 = acc[mi][ni][2] + sBias[cl];
            float v3 = acc[mi][ni][3] + sBias[cl + 1];
            if (MODE == 1) {
                size_t o0 = (size_t)(rowA + r) * HV + gc;
                size_t o1 = (size_t)(rowA + r + 8) * HV + gc;
                *(float2*)(g_hidden + o0) = make_float2(v0, v1);
                *(float2*)(g_hidden + o1) = make_float2(v2, v3);
                *(__half2*)(g_hid16 + o0) = __floats2half2_rn(v0, v1);
                *(__half2*)(g_hid16 + o1) = __floats2half2_rn(v2, v3);
                ssAcc[mi][0] += v0 * v0 + v1 * v1;
                ssAcc[mi][1] += v2 * v2 + v3 * v3;
            } else {
                v0 = fmaxf(v0, 0.f); v1 = fmaxf(v1, 0.f);
                v2 = fmaxf(v2, 0.f); v3 = fmaxf(v3, 0.f);
                size_t o0 = (size_t)(rowA + r) * HV + gc;
                size_t o1 = (size_t)(rowA + r + 8) * HV + gc;
                *(__half2*)(g_h16 + o0) = __floats2half2_rn(v0, v1);
                *(__half2*)(g_h16 + o1) = __floats2half2_rn(v2, v3);
            }
        }
    }
    if (MODE == 1) {
        float* rowSS = (float*)smem;
        __syncthreads();
        if (tid < 128) rowSS[tid] = 0.f;
        __syncthreads();
#pragma unroll
        for (int mi = 0; mi < 4; mi++) {
            atomicAdd(&rowSS[rBase0 + mi * 16], ssAcc[mi][0]);
            atomicAdd(&rowSS[rBase0 + mi * 16 + 8], ssAcc[mi][1]);
        }
        __syncthreads();
        if (tid < 128) atomicAdd(&g_ss[rowA + tid], rowSS[tid]);
    }
}

// ============================================================
// sim_t: triangular cosine-sim on 128x256 super-tiles, fp16 accum,
// TMA-bulk loader, 2-stage ring.
// ============================================================
constexpr int S_B_OFF = 128 * PITCH;               // 18432
constexpr int S_STAGE = S_B_OFF + 256 * PITCH;     // 55296
constexpr int S_SMEM = 2 * S_STAGE;                // 110592 (108 KB)
constexpr uint32_t S_TX = 384 * 128;               // bytes per stage
constexpr int SIM_TILES = 72;

__global__ __launch_bounds__(256, 2)
void sim_t()
{
    constexpr int KDIM = HV;
    constexpr int NC = KDIM / 64;                  // 8
    extern __shared__ __align__(1024) char smem[];
    const uint32_t sbase = smem_u32(smem);
    __shared__ float sInvA[128], sInvB[256];
    __shared__ __align__(8) uint64_t s_mbar[2];
    const uint32_t mb = smem_u32(s_mbar);

    const int tid = threadIdx.x;
    const int lane = tid & 31;
    const int wid = tid >> 5;

    const int bIdx = blockIdx.y;
    int rem = blockIdx.x, ti = 0;
    while (rem >= (8 - (ti >> 1))) { rem -= (8 - (ti >> 1)); ti++; }
    const int tjj = (ti >> 1) + rem;
    const int rowA = bIdx * NV + ti * 128;
    const int rowB = bIdx * NV + tjj * 256;
    const int tj0 = 2 * tjj;

    const __half* srcA = g_hid16 + (size_t)rowA * KDIM;
    const __half* srcB = g_hid16 + (size_t)rowB * KDIM;

    sInvB[tid] = rsqrtf(fmaxf(g_ss[rowB + tid], 1e-24f));
    if (tid < 128) sInvA[tid] = rsqrtf(fmaxf(g_ss[rowA + tid], 1e-24f));
    if (tid == 0) { MBAR_INIT(mb, 1); MBAR_INIT(mb + 8, 1); }
    __syncthreads();

    // ---- bulk stage loader: 384 rows, threads 0..255 do 1-2 rows ----
    auto load_stage = [&](int slot, int c) {
        const uint32_t stBase = sbase + slot * S_STAGE;
        const int k0 = c * 64;
        const uint32_t bar = mb + slot * 8;
        if (tid == 0) MBAR_EXPECT(bar, S_TX);
        {
            const int r = tid;   // 0..255: A rows 0..127, B rows 0..127
            const __half* gsrc = (r < 128) ? srcA + (size_t)r * KDIM + k0
                                           : srcB + (size_t)(r - 128) * KDIM + k0;
            uint32_t dst = stBase + ((r < 128) ? r * PITCH
                                               : S_B_OFF + (r - 128) * PITCH);
            BULK128(dst, gsrc, bar);
        }
        if (tid < 128) {         // B rows 128..255
            const int r = 128 + tid;
            const __half* gsrc = srcB + (size_t)r * KDIM + k0;
            uint32_t dst = stBase + S_B_OFF + r * PITCH;
            BULK128(dst, gsrc, bar);
        }
    };

    const int warpM = (wid >> 2) * 64;
    const int warpN = (wid & 3) * 64;
    uint32_t aRow[4], bRow[4];
#pragma unroll
    for (int mi = 0; mi < 4; mi++)
        aRow[mi] = (uint32_t)((warpM + mi * 16 + (lane & 15)) * PITCH);
    const int bLocal = (lane & 7) + ((lane >> 4) << 3);
#pragma unroll
    for (int p = 0; p < 4; p++)
        bRow[p] = (uint32_t)((warpN + p * 16 + bLocal) * PITCH);
    const uint32_t aKsel = (uint32_t)((lane >> 4) << 4);
    const uint32_t bKsel = (uint32_t)(((lane >> 3) & 1) << 4);

    uint32_t accH[4][8][2];
#pragma unroll
    for (int mi = 0; mi < 4; mi++)
#pragma unroll
        for (int ni = 0; ni < 8; ni++) { accH[mi][ni][0] = 0u; accH[mi][ni][1] = 0u; }

    auto compute_stage = [&](int slot) {
        const uint32_t stBase = sbase + slot * S_STAGE;
        const uint32_t tA = stBase, tB = stBase + S_B_OFF;
#pragma unroll
        for (int ks = 0; ks < 4; ks++) {
            const uint32_t kk = (uint32_t)(ks * 32);
            uint32_t bh[8][2];
#pragma unroll
            for (int p = 0; p < 4; p++) {
                uint32_t r0, r1, r2, r3;
                LDSM4(r0, r1, r2, r3, tB + bRow[p] + kk + bKsel);
                bh[p * 2][0] = r0; bh[p * 2][1] = r1;
                bh[p * 2 + 1][0] = r2; bh[p * 2 + 1][1] = r3;
            }
            uint32_t a[4][4];
#pragma unroll
            for (int mi = 0; mi < 4; mi++)
                LDSM4(a[mi][0], a[mi][1], a[mi][2], a[mi][3],
                      tA + aRow[mi] + kk + aKsel);
#pragma unroll
            for (int mi = 0; mi < 4; mi++)
#pragma unroll
                for (int ni = 0; ni < 8; ni++)
                    mma_f16h(accH[mi][ni], a[mi], bh[ni]);
        }
    };

    // ---- 2-stage mainloop ----
    load_stage(0, 0);
    load_stage(1, 1);
    for (int c = 0; c < NC; c++) {
        const int slot = c & 1;
        MBAR_WAIT(mb + slot * 8, (uint32_t)((c >> 1) & 1));
        compute_stage(slot);
        __syncthreads();                 // all done with slot before refilling it
        if (c + 2 < NC) load_stage(slot, c + 2);
    }

    // ---- epilogue: rescale, softplus, masked dual reduction ----
    const int rBase0 = warpM + (lane >> 2);
    const int cBase = warpN + (lane & 3) * 2;
    float* rowAcc = (float*)smem;              // [128]
    float* colAcc = (float*)smem + 128;        // [256]
    __syncthreads();
    if (tid < 128) rowAcc[tid] = 0.f;
    colAcc[tid] = 0.f;
    __syncthreads();

    const bool colOK0 = (tj0 >= ti), colOK1 = (tj0 + 1 >= ti);
    const bool rowOK0 = (tj0 > ti),  rowOK1 = (tj0 + 1 > ti);

    float rowPart[4][2];
    float colPart[8][2];
#pragma unroll
    for (int i = 0; i < 4; i++) { rowPart[i][0] = rowPart[i][1] = 0.f; }
#pragma unroll
    for (int i = 0; i < 8; i++) { colPart[i][0] = colPart[i][1] = 0.f; }

#pragma unroll
    for (int mi = 0; mi < 4; mi++) {
        const float ia0 = sInvA[rBase0 + mi * 16];
        const float ia1 = sInvA[rBase0 + mi * 16 + 8];
#pragma unroll
        for (int ni = 0; ni < 8; ni++) {
            const int cl = cBase + ni * 8;
            const bool colOK = (cl < 128) ? colOK0 : colOK1;
            const bool rowOK = (cl < 128) ? rowOK0 : rowOK1;
            if (!colOK && !rowOK) continue;
            const float ib0 = sInvB[cl];
            const float ib1 = sInvB[cl + 1];
            float2 lo = __half22float2(*(__half2*)&accH[mi][ni][0]);
            float2 hi = __half22float2(*(__half2*)&accH[mi][ni][1]);
            float v0 = softplus_fast(lo.x * ia0 * ib0);
            float v1 = softplus_fast(lo.y * ia0 * ib1);
            float v2 = softplus_fast(hi.x * ia1 * ib0);
            float v3 = softplus_fast(hi.y * ia1 * ib1);
            if (rowOK) {
                rowPart[mi][0] += v0 + v1;
                rowPart[mi][1] += v2 + v3;
            }
            if (colOK) {
                colPart[ni][0] += v0 + v2;
                colPart[ni][1] += v1 + v3;
            }
        }
    }
#pragma unroll
    for (int mi = 0; mi < 4; mi++) {
        atomicAdd(&rowAcc[rBase0 + mi * 16], rowPart[mi][0]);
        atomicAdd(&rowAcc[rBase0 + mi * 16 + 8], rowPart[mi][1]);
    }
#pragma unroll
    for (int ni = 0; ni < 8; ni++) {
        atomicAdd(&colAcc[cBase + ni * 8], colPart[ni][0]);
        atomicAdd(&colAcc[cBase + ni * 8 + 1], colPart[ni][1]);
    }
    __syncthreads();
    if (tid < 128) {
        if (colOK0) atomicAdd(&g_c[bIdx * NV + tj0 * 128 + tid], colAcc[tid]);
        if (rowOK0 || rowOK1) atomicAdd(&g_c[bIdx * NV + ti * 128 + tid], rowAcc[tid]);
    } else {
        if (colOK1) atomicAdd(&g_c[bIdx * NV + (tj0 + 1) * 128 + (tid - 128)], colAcc[tid]);
    }
}

// ---------------- witness: partial sums over m-chunks ----------------
__global__ __launch_bounds__(512)
void witness_kernel()
{
    const int chunk = blockIdx.x;   // 32 chunks of 64 rows
    const int b = blockIdx.y;
    const int h = threadIdx.x;
    __shared__ float cs[64];
    if (threadIdx.x < 64) cs[threadIdx.x] = g_c[b * NV + chunk * 64 + threadIdx.x];
    __syncthreads();
    const float* hp = g_hidden + (size_t)(b * NV + chunk * 64) * HV + h;
    float a = 0.f;
#pragma unroll 8
    for (int m = 0; m < 64; m++)
        a = fmaf(cs[m], hp[(size_t)m * HV], a);
    atomicAdd(&g_wit[b * HV + h], a);
}

// ---------------- output projection ----------------
__global__ __launch_bounds__(512)
void proj_kernel(const float* __restrict__ Wp, const float* __restrict__ bp,
                 float* __restrict__ out)
{
    const int b = blockIdx.x;
    const int g = threadIdx.x;
    __shared__ float w[HV];
    w[g] = g_wit[b * HV + g] * (1.0f / NV);
    __syncthreads();
    float accv = bp[g];
    const float* wp = Wp + (size_t)g * HV;
#pragma unroll 8
    for (int h = 0; h < HV; h++)
        accv = fmaf(w[h], wp[h], accv);
    out[b * HV + g] = accv;
}

extern "C" void kernel_launch(void* const* d_in, const int* in_sizes, int n_in,
                              void* d_out, int out_size)
{
    const int*   tokens = (const int*)d_in[0];
    const float* emb    = (const float*)d_in[1];
    const float* W1     = (const float*)d_in[2];
    const float* b1     = (const float*)d_in[3];
    const float* W2     = (const float*)d_in[4];
    const float* b2     = (const float*)d_in[5];
    const float* Wp     = (const float*)d_in[6];
    const float* bp     = (const float*)d_in[7];
    float* out = (float*)d_out;
    (void)in_sizes; (void)n_in; (void)out_size;

    cudaFuncSetAttribute(gemm_t<0>, cudaFuncAttributeMaxDynamicSharedMemorySize, G_SMEM);
    cudaFuncSetAttribute(gemm_t<1>, cudaFuncAttributeMaxDynamicSharedMemorySize, G_SMEM);
    cudaFuncSetAttribute(sim_t, cudaFuncAttributeMaxDynamicSharedMemorySize, S_SMEM);

    conv_all_kernel<<<EMB_BLK + W1_BLK + W2_BLK + Z_BLK, 256>>>(tokens, emb, W1, W2);

    gemm_t<0><<<dim3(MROWS / 128, HV / 128), 256, G_SMEM>>>(b1);
    gemm_t<1><<<dim3(MROWS / 128, HV / 128), 256, G_SMEM>>>(b2);

    sim_t<<<dim3(SIM_TILES, BV), 256, S_SMEM>>>();   // launch #4 -> profiled

    witness_kernel<<<dim3(32, BV), 512>>>();
    proj_kernel<<<BV, 512>>>(Wp, bp, out);
}

// round 15
// speedup vs baseline: 1.1601x; 1.1601x over previous
#include <cuda_runtime.h>
#include <cuda_fp16.h>
#include <cstdint>

#define BV 8
#define NV 2048
#define EV 256
#define HV 512
#define MROWS (BV*NV)   // 16384

// ---------------- scratch (static device globals) ----------------
__device__ __half g_A16[(size_t)MROWS * EV];     // fp16 gathered embeddings
__device__ __half g_W1h[HV * EV];
__device__ __half g_W2h[HV * HV];
__device__ __half g_h16[(size_t)MROWS * HV];     // relu(emb@W1+b1), fp16
__device__ __half g_hid16[(size_t)MROWS * HV];   // fp16 hidden (sim + witness)
__device__ float  g_ss[MROWS];                   // per-row sum of squares
__device__ float g_c[BV * NV];
__device__ float g_wit[BV * HV];

// ---------------- helpers ----------------
__device__ __forceinline__ uint32_t smem_u32(const void* p) {
    uint32_t a;
    asm("{ .reg .u64 t; cvta.to.shared.u64 t, %1; cvt.u32.u64 %0, t; }" : "=r"(a) : "l"(p));
    return a;
}
__device__ __forceinline__ void mma_f16(float* c, const uint32_t* a, const uint32_t* b) {
    asm volatile("mma.sync.aligned.m16n8k16.row.col.f32.f16.f16.f32 "
                 "{%0,%1,%2,%3}, {%4,%5,%6,%7}, {%8,%9}, {%0,%1,%2,%3};"
                 : "+f"(c[0]), "+f"(c[1]), "+f"(c[2]), "+f"(c[3])
                 : "r"(a[0]), "r"(a[1]), "r"(a[2]), "r"(a[3]),
                   "r"(b[0]), "r"(b[1]));
}
__device__ __forceinline__ void mma_f16h(uint32_t* c, const uint32_t* a, const uint32_t* b) {
    asm volatile("mma.sync.aligned.m16n8k16.row.col.f16.f16.f16.f16 "
                 "{%0,%1}, {%2,%3,%4,%5}, {%6,%7}, {%0,%1};"
                 : "+r"(c[0]), "+r"(c[1])
                 : "r"(a[0]), "r"(a[1]), "r"(a[2]), "r"(a[3]),
                   "r"(b[0]), "r"(b[1]));
}
#define LDSM4(r0, r1, r2, r3, addr) \
    asm volatile("ldmatrix.sync.aligned.m8n8.x4.shared.b16 {%0,%1,%2,%3}, [%4];" \
                 : "=r"(r0), "=r"(r1), "=r"(r2), "=r"(r3) : "r"(addr))
#define CP_COMMIT asm volatile("cp.async.commit_group;" ::: "memory")
#define CP_WAIT1  asm volatile("cp.async.wait_group 1;" ::: "memory")

// MUFU-free softplus for |x| <= ~1.1 (sim = cosine similarity).
__device__ __forceinline__ float softplus_fast(float x) {
    float u = 0.5f * x;
    float v = u * u;
    float p = fmaf(v, 0.002186948854f, -0.006746031746f);
    p = fmaf(v, p, 0.022222222222f);
    p = fmaf(v, p, -0.083333333333f);
    p = fmaf(v, p, 0.5f);
    return fmaf(v, p, u + 0.69314718056f);
}

// ---------------- fused conversion + zero kernel ----------------
constexpr int EMB_BLK = MROWS / 4;                 // 4096
constexpr int W1_BLK = (HV * EV / 4) / 256;        // 128
constexpr int W2_BLK = (HV * HV / 4) / 256;        // 256
constexpr int Z_TOTAL = BV * NV + BV * HV + MROWS; // 36864
constexpr int Z_BLK = Z_TOTAL / 256;               // 144

__global__ __launch_bounds__(256)
void conv_all_kernel(const int* __restrict__ tokens, const float* __restrict__ emb,
                     const float* __restrict__ W1, const float* __restrict__ W2)
{
    const int blk = blockIdx.x;
    if (blk < EMB_BLK) {
        const int idx = blk * 256 + threadIdx.x;
        const int row = idx >> 6;
        const int t = idx & 63;
        const int tok = tokens[row];
        float4 v = *(const float4*)(emb + (size_t)tok * EV + t * 4);
        size_t o = (size_t)row * EV + t * 4;
        *(__half2*)(g_A16 + o)     = __floats2half2_rn(v.x, v.y);
        *(__half2*)(g_A16 + o + 2) = __floats2half2_rn(v.z, v.w);
    } else if (blk < EMB_BLK + W1_BLK) {
        int i = (blk - EMB_BLK) * 256 + threadIdx.x;
        float4 v = ((const float4*)W1)[i];
        size_t o = (size_t)i * 4;
        *(__half2*)(g_W1h + o)     = __floats2half2_rn(v.x, v.y);
        *(__half2*)(g_W1h + o + 2) = __floats2half2_rn(v.z, v.w);
    } else if (blk < EMB_BLK + W1_BLK + W2_BLK) {
        int i = (blk - EMB_BLK - W1_BLK) * 256 + threadIdx.x;
        float4 v = ((const float4*)W2)[i];
        size_t o = (size_t)i * 4;
        *(__half2*)(g_W2h + o)     = __floats2half2_rn(v.x, v.y);
        *(__half2*)(g_W2h + o + 2) = __floats2half2_rn(v.z, v.w);
    } else {
        int i = (blk - EMB_BLK - W1_BLK - W2_BLK) * 256 + threadIdx.x;
        if (i < BV * NV) g_c[i] = 0.f;
        else if (i < BV * NV + BV * HV) g_wit[i - BV * NV] = 0.f;
        else if (i < Z_TOTAL) g_ss[i - BV * NV - BV * HV] = 0.f;
    }
}

// ============================================================
// gemm_t: dense GEMMs, fp32 accumulators, cp.async loaders (R13 form).
// MODE 0: relu(A16 @ W1^T + b1) -> g_h16               (K=256)
// MODE 1: h16 @ W2^T + b2 -> g_hid16 fp16 + g_ss       (K=512)
// ============================================================
constexpr int STAGE_BYTES = 2 * 16384;
constexpr int NSTAGE = 3;
constexpr int SMEM_SZ = NSTAGE * STAGE_BYTES;   // 96 KB

template<int MODE>
__global__ __launch_bounds__(256, 2)
void gemm_t(const float* __restrict__ bias)
{
    constexpr int KDIM = (MODE == 0) ? EV : HV;
    constexpr int NC = KDIM / 64;
    extern __shared__ __align__(1024) char smem[];
    const uint32_t sbase = smem_u32(smem);
    __shared__ float sBias[128];

    const int tid = threadIdx.x;
    const int lane = tid & 31;
    const int wid = tid >> 5;

    const int rowA = blockIdx.x * 128;
    const int rowB = blockIdx.y * 128;

    const __half* srcA = (MODE == 0) ? g_A16 + (size_t)rowA * KDIM
                                     : g_h16 + (size_t)rowA * KDIM;
    const __half* srcB = (MODE == 0) ? g_W1h + (size_t)rowB * KDIM
                                     : g_W2h + (size_t)rowB * KDIM;
    if (tid < 128) sBias[tid] = bias[blockIdx.y * 128 + tid];

    auto load_stage = [&](int stage, int c) {
        const uint32_t stBase = sbase + stage * STAGE_BYTES;
        const int k0 = c * 64;
#pragma unroll
        for (int l = 0; l < 8; l++) {
            int s = l * 256 + tid;
            int comp = s >> 10;
            int u = s & 1023;
            int r = u >> 3, seg = u & 7;
            const __half* gsrc = (comp ? srcB : srcA) + (size_t)r * KDIM + k0 + seg * 8;
            uint32_t off = (uint32_t)(r * 128 + seg * 16);
            uint32_t dst = stBase + comp * 16384 + (off ^ ((off >> 3) & 0x70));
            asm volatile("cp.async.cg.shared.global [%0], [%1], 16;"
                         :: "r"(dst), "l"(gsrc));
        }
    };

    const int warpM = (wid >> 2) * 64;
    const int warpN = (wid & 3) * 32;
    const uint32_t xorT = (uint32_t)((lane & 7) << 4);
    uint32_t aRow[4], bRow[2];
#pragma unroll
    for (int mi = 0; mi < 4; mi++)
        aRow[mi] = (uint32_t)((warpM + mi * 16 + (lane & 15)) * 128);
    const int bLocal = (lane & 7) + ((lane >> 4) << 3);
#pragma unroll
    for (int p = 0; p < 2; p++)
        bRow[p] = (uint32_t)((warpN + p * 16 + bLocal) * 128);
    const uint32_t aKsel = (uint32_t)((lane >> 4) << 4);
    const uint32_t bKsel = (uint32_t)(((lane >> 3) & 1) << 4);

    float acc[4][4][4];
#pragma unroll
    for (int mi = 0; mi < 4; mi++)
#pragma unroll
        for (int ni = 0; ni < 4; ni++)
#pragma unroll
            for (int k = 0; k < 4; k++) acc[mi][ni][k] = 0.f;

    auto compute_stage = [&](int stage) {
        const uint32_t stBase = sbase + stage * STAGE_BYTES;
        const uint32_t tA = stBase, tB = stBase + 16384;
#pragma unroll
        for (int ks = 0; ks < 4; ks++) {
            const uint32_t kk = (uint32_t)(ks * 32);
            uint32_t bh[4][2];
            {
                uint32_t r0, r1, r2, r3;
                LDSM4(r0, r1, r2, r3, tB + bRow[0] + ((kk + bKsel) ^ xorT));
                bh[0][0] = r0; bh[0][1] = r1; bh[1][0] = r2; bh[1][1] = r3;
                LDSM4(r0, r1, r2, r3, tB + bRow[1] + ((kk + bKsel) ^ xorT));
                bh[2][0] = r0; bh[2][1] = r1; bh[3][0] = r2; bh[3][1] = r3;
            }
            uint32_t a[4][4];
#pragma unroll
            for (int mi = 0; mi < 4; mi++)
                LDSM4(a[mi][0], a[mi][1], a[mi][2], a[mi][3],
                      tA + aRow[mi] + ((kk + aKsel) ^ xorT));
#pragma unroll
            for (int mi = 0; mi < 4; mi++)
#pragma unroll
                for (int ni = 0; ni < 4; ni++)
                    mma_f16(acc[mi][ni], a[mi], bh[ni]);
        }
    };

    load_stage(0, 0); CP_COMMIT;
    load_stage(1, 1); CP_COMMIT;
    for (int c = 0; c < NC; c++) {
        CP_WAIT1;
        __syncthreads();
        if (c + 2 < NC) load_stage((c + 2) % NSTAGE, c + 2);
        CP_COMMIT;
        compute_stage(c % NSTAGE);
    }

    const int rBase0 = warpM + (lane >> 2);
    const int cBase = warpN + (lane & 3) * 2;

    float ssAcc[4][2];
#pragma unroll
    for (int mi = 0; mi < 4; mi++) { ssAcc[mi][0] = 0.f; ssAcc[mi][1] = 0.f; }
#pragma unroll
    for (int mi = 0; mi < 4; mi++) {
        const int r = rBase0 + mi * 16;
#pragma unroll
        for (int ni = 0; ni < 4; ni++) {
            const int cl = cBase + ni * 8;
            const int gc = blockIdx.y * 128 + cl;
            float v0 = acc[mi][ni][0] + sBias[cl];
            float v1 = acc[mi][ni][1] + sBias[cl + 1];
            float v2 = acc[mi][ni][2] + sBias[cl];
            float v3 = acc[mi][ni][3] + sBias[cl + 1];
            size_t o0 = (size_t)(rowA + r) * HV + gc;
            size_t o1 = (size_t)(rowA + r + 8) * HV + gc;
            if (MODE == 1) {
                *(__half2*)(g_hid16 + o0) = __floats2half2_rn(v0, v1);
                *(__half2*)(g_hid16 + o1) = __floats2half2_rn(v2, v3);
                ssAcc[mi][0] += v0 * v0 + v1 * v1;
                ssAcc[mi][1] += v2 * v2 + v3 * v3;
            } else {
                v0 = fmaxf(v0, 0.f); v1 = fmaxf(v1, 0.f);
                v2 = fmaxf(v2, 0.f); v3 = fmaxf(v3, 0.f);
                *(__half2*)(g_h16 + o0) = __floats2half2_rn(v0, v1);
                *(__half2*)(g_h16 + o1) = __floats2half2_rn(v2, v3);
            }
        }
    }
    if (MODE == 1) {
        float* rowSS = (float*)smem;
        __syncthreads();
        if (tid < 128) rowSS[tid] = 0.f;
        __syncthreads();
#pragma unroll
        for (int mi = 0; mi < 4; mi++) {
            atomicAdd(&rowSS[rBase0 + mi * 16], ssAcc[mi][0]);
            atomicAdd(&rowSS[rBase0 + mi * 16 + 8], ssAcc[mi][1]);
        }
        __syncthreads();
        if (tid < 128) atomicAdd(&g_ss[rowA + tid], rowSS[tid]);
    }
}

// ============================================================
// sim_t: triangular cosine-sim on 128x256 super-tiles (R13 form).
// Warp tile 64x64 (fp16 accum), 8 warps, 2-stage 96KB cp.async ring.
// ============================================================
constexpr int SIM_STAGE = 48 * 1024;          // A 16KB + B 32KB
constexpr int SIM_SMEM = 2 * SIM_STAGE;       // 96 KB
constexpr int SIM_TILES = 72;

__global__ __launch_bounds__(256, 2)
void sim_t()
{
    constexpr int KDIM = HV;
    constexpr int NC = KDIM / 64;             // 8 chunks
    extern __shared__ __align__(1024) char smem[];
    const uint32_t sbase = smem_u32(smem);
    __shared__ float sInvA[128], sInvB[256];

    const int tid = threadIdx.x;
    const int lane = tid & 31;
    const int wid = tid >> 5;

    const int bIdx = blockIdx.y;
    int rem = blockIdx.x, ti = 0;
    while (rem >= (8 - (ti >> 1))) { rem -= (8 - (ti >> 1)); ti++; }
    const int tjj = (ti >> 1) + rem;
    const int rowA = bIdx * NV + ti * 128;
    const int rowB = bIdx * NV + tjj * 256;
    const int tj0 = 2 * tjj;

    const __half* srcA = g_hid16 + (size_t)rowA * KDIM;
    const __half* srcB = g_hid16 + (size_t)rowB * KDIM;

    sInvB[tid] = rsqrtf(fmaxf(g_ss[rowB + tid], 1e-24f));
    if (tid < 128) sInvA[tid] = rsqrtf(fmaxf(g_ss[rowA + tid], 1e-24f));

    auto load_stage = [&](int stage, int c) {
        const uint32_t stBase = sbase + stage * SIM_STAGE;
        const int k0 = c * 64;
#pragma unroll
        for (int l = 0; l < 12; l++) {
            int s = l * 256 + tid;
            const __half* gsrc;
            uint32_t dstT;
            int r, seg;
            if (s < 1024) {
                r = s >> 3; seg = s & 7;
                gsrc = srcA + (size_t)r * KDIM + k0 + seg * 8;
                dstT = stBase;
            } else {
                int u = s - 1024;
                r = u >> 3; seg = u & 7;
                gsrc = srcB + (size_t)r * KDIM + k0 + seg * 8;
                dstT = stBase + 16384;
            }
            uint32_t off = (uint32_t)(r * 128 + seg * 16);
            uint32_t dst = dstT + (off ^ ((off >> 3) & 0x70));
            asm volatile("cp.async.cg.shared.global [%0], [%1], 16;"
                         :: "r"(dst), "l"(gsrc));
        }
    };

    const int warpM = (wid >> 2) * 64;
    const int warpN = (wid & 3) * 64;
    const uint32_t xorT = (uint32_t)((lane & 7) << 4);
    uint32_t aRow[4], bRow[4];
#pragma unroll
    for (int mi = 0; mi < 4; mi++)
        aRow[mi] = (uint32_t)((warpM + mi * 16 + (lane & 15)) * 128);
    const int bLocal = (lane & 7) + ((lane >> 4) << 3);
#pragma unroll
    for (int p = 0; p < 4; p++)
        bRow[p] = (uint32_t)((warpN + p * 16 + bLocal) * 128);
    const uint32_t aKsel = (uint32_t)((lane >> 4) << 4);
    const uint32_t bKsel = (uint32_t)(((lane >> 3) & 1) << 4);

    uint32_t accH[4][8][2];
#pragma unroll
    for (int mi = 0; mi < 4; mi++)
#pragma unroll
        for (int ni = 0; ni < 8; ni++) { accH[mi][ni][0] = 0u; accH[mi][ni][1] = 0u; }

    auto compute_stage = [&](int stage) {
        const uint32_t stBase = sbase + stage * SIM_STAGE;
        const uint32_t tA = stBase, tB = stBase + 16384;
#pragma unroll
        for (int ks = 0; ks < 4; ks++) {
            const uint32_t kk = (uint32_t)(ks * 32);
            uint32_t bh[8][2];
#pragma unroll
            for (int p = 0; p < 4; p++) {
                uint32_t r0, r1, r2, r3;
                LDSM4(r0, r1, r2, r3, tB + bRow[p] + ((kk + bKsel) ^ xorT));
                bh[p * 2][0] = r0; bh[p * 2][1] = r1;
                bh[p * 2 + 1][0] = r2; bh[p * 2 + 1][1] = r3;
            }
            uint32_t a[4][4];
#pragma unroll
            for (int mi = 0; mi < 4; mi++)
                LDSM4(a[mi][0], a[mi][1], a[mi][2], a[mi][3],
                      tA + aRow[mi] + ((kk + aKsel) ^ xorT));
#pragma unroll
            for (int mi = 0; mi < 4; mi++)
#pragma unroll
                for (int ni = 0; ni < 8; ni++)
                    mma_f16h(accH[mi][ni], a[mi], bh[ni]);
        }
    };

    load_stage(0, 0); CP_COMMIT;
    load_stage(1, 1); CP_COMMIT;
    for (int c = 0; c < NC; c++) {
        CP_WAIT1;
        __syncthreads();
        compute_stage(c & 1);
        __syncthreads();
        if (c + 2 < NC) load_stage(c & 1, c + 2);
        CP_COMMIT;
    }

    // ---- epilogue: rescale, softplus, masked dual reduction ----
    const int rBase0 = warpM + (lane >> 2);
    const int cBase = warpN + (lane & 3) * 2;
    float* rowAcc = (float*)smem;              // [128]
    float* colAcc = (float*)smem + 128;        // [256]
    __syncthreads();
    if (tid < 128) rowAcc[tid] = 0.f;
    colAcc[tid] = 0.f;
    __syncthreads();

    const bool colOK0 = (tj0 >= ti), colOK1 = (tj0 + 1 >= ti);
    const bool rowOK0 = (tj0 > ti),  rowOK1 = (tj0 + 1 > ti);

    float rowPart[4][2];
    float colPart[8][2];
#pragma unroll
    for (int i = 0; i < 4; i++) { rowPart[i][0] = rowPart[i][1] = 0.f; }
#pragma unroll
    for (int i = 0; i < 8; i++) { colPart[i][0] = colPart[i][1] = 0.f; }

#pragma unroll
    for (int mi = 0; mi < 4; mi++) {
        const float ia0 = sInvA[rBase0 + mi * 16];
        const float ia1 = sInvA[rBase0 + mi * 16 + 8];
#pragma unroll
        for (int ni = 0; ni < 8; ni++) {
            const int cl = cBase + ni * 8;
            const bool colOK = (cl < 128) ? colOK0 : colOK1;
            const bool rowOK = (cl < 128) ? rowOK0 : rowOK1;
            if (!colOK && !rowOK) continue;
            const float ib0 = sInvB[cl];
            const float ib1 = sInvB[cl + 1];
            float2 lo = __half22float2(*(__half2*)&accH[mi][ni][0]);
            float2 hi = __half22float2(*(__half2*)&accH[mi][ni][1]);
            float v0 = softplus_fast(lo.x * ia0 * ib0);
            float v1 = softplus_fast(lo.y * ia0 * ib1);
            float v2 = softplus_fast(hi.x * ia1 * ib0);
            float v3 = softplus_fast(hi.y * ia1 * ib1);
            if (rowOK) {
                rowPart[mi][0] += v0 + v1;
                rowPart[mi][1] += v2 + v3;
            }
            if (colOK) {
                colPart[ni][0] += v0 + v2;
                colPart[ni][1] += v1 + v3;
            }
        }
    }
#pragma unroll
    for (int mi = 0; mi < 4; mi++) {
        atomicAdd(&rowAcc[rBase0 + mi * 16], rowPart[mi][0]);
        atomicAdd(&rowAcc[rBase0 + mi * 16 + 8], rowPart[mi][1]);
    }
#pragma unroll
    for (int ni = 0; ni < 8; ni++) {
        atomicAdd(&colAcc[cBase + ni * 8], colPart[ni][0]);
        atomicAdd(&colAcc[cBase + ni * 8 + 1], colPart[ni][1]);
    }
    __syncthreads();
    if (tid < 128) {
        if (colOK0) atomicAdd(&g_c[bIdx * NV + tj0 * 128 + tid], colAcc[tid]);
        if (rowOK0 || rowOK1) atomicAdd(&g_c[bIdx * NV + ti * 128 + tid], rowAcc[tid]);
    } else {
        if (colOK1) atomicAdd(&g_c[bIdx * NV + (tj0 + 1) * 128 + (tid - 128)], colAcc[tid]);
    }
}

// ---------------- witness: fp16 hidden reads, partial sums ----------------
__global__ __launch_bounds__(256)
void witness_kernel()
{
    const int chunk = blockIdx.x;   // 32 chunks of 64 rows
    const int b = blockIdx.y;
    const int h2 = threadIdx.x;     // half2 index: covers HV=512 as 256 pairs
    __shared__ float cs[64];
    if (threadIdx.x < 64) cs[threadIdx.x] = g_c[b * NV + chunk * 64 + threadIdx.x];
    __syncthreads();
    const __half* hp = g_hid16 + (size_t)(b * NV + chunk * 64) * HV + h2 * 2;
    float a0 = 0.f, a1 = 0.f;
#pragma unroll 8
    for (int m = 0; m < 64; m++) {
        float2 v = __half22float2(*(const __half2*)(hp + (size_t)m * HV));
        a0 = fmaf(cs[m], v.x, a0);
        a1 = fmaf(cs[m], v.y, a1);
    }
    atomicAdd(&g_wit[b * HV + h2 * 2], a0);
    atomicAdd(&g_wit[b * HV + h2 * 2 + 1], a1);
}

// ---------------- output projection ----------------
__global__ __launch_bounds__(512)
void proj_kernel(const float* __restrict__ Wp, const float* __restrict__ bp,
                 float* __restrict__ out)
{
    const int b = blockIdx.x;
    const int g = threadIdx.x;
    __shared__ float w[HV];
    w[g] = g_wit[b * HV + g] * (1.0f / NV);
    __syncthreads();
    float accv = bp[g];
    const float* wp = Wp + (size_t)g * HV;
#pragma unroll 8
    for (int h = 0; h < HV; h++)
        accv = fmaf(w[h], wp[h], accv);
    out[b * HV + g] = accv;
}

extern "C" void kernel_launch(void* const* d_in, const int* in_sizes, int n_in,
                              void* d_out, int out_size)
{
    const int*   tokens = (const int*)d_in[0];
    const float* emb    = (const float*)d_in[1];
    const float* W1     = (const float*)d_in[2];
    const float* b1     = (const float*)d_in[3];
    const float* W2     = (const float*)d_in[4];
    const float* b2     = (const float*)d_in[5];
    const float* Wp     = (const float*)d_in[6];
    const float* bp     = (const float*)d_in[7];
    float* out = (float*)d_out;
    (void)in_sizes; (void)n_in; (void)out_size;

    cudaFuncSetAttribute(gemm_t<0>, cudaFuncAttributeMaxDynamicSharedMemorySize, SMEM_SZ);
    cudaFuncSetAttribute(gemm_t<1>, cudaFuncAttributeMaxDynamicSharedMemorySize, SMEM_SZ);
    cudaFuncSetAttribute(sim_t, cudaFuncAttributeMaxDynamicSharedMemorySize, SIM_SMEM);

    conv_all_kernel<<<EMB_BLK + W1_BLK + W2_BLK + Z_BLK, 256>>>(tokens, emb, W1, W2);

    gemm_t<0><<<dim3(MROWS / 128, HV / 128), 256, SMEM_SZ>>>(b1);
    gemm_t<1><<<dim3(MROWS / 128, HV / 128), 256, SMEM_SZ>>>(b2);

    sim_t<<<dim3(SIM_TILES, BV), 256, SIM_SMEM>>>();   // launch #4 -> profiled

    witness_kernel<<<dim3(32, BV), 256>>>();
    proj_kernel<<<BV, 512>>>(Wp, bp, out);
}